// round 2
// baseline (speedup 1.0000x reference)
#include <cuda_runtime.h>

// TinyFormerEncoder: B=65536, S=16, D=32, FFN=64, fp32.
// 1 thread = 1 (batch, row); 128 threads/block = 8 batches/block; 8192 blocks.
// Static smem only (45KB): K/V swizzled (32KB) + 12KB phased weight buffer.
// All math in packed fp32x2 FMA (sm_100+). No dynamic smem, no attribute calls.

typedef unsigned long long u64;

__device__ __forceinline__ u64 pack2(float lo, float hi) {
    u64 r; asm("mov.b64 %0, {%1, %2};" : "=l"(r) : "f"(lo), "f"(hi)); return r;
}
__device__ __forceinline__ void unpack2(u64 v, float& lo, float& hi) {
    asm("mov.b64 {%0, %1}, %2;" : "=f"(lo), "=f"(hi) : "l"(v));
}
__device__ __forceinline__ u64 dup2(float x) { return pack2(x, x); }
// d += a * b (packed 2x fp32)
__device__ __forceinline__ void ffma2(u64& d, u64 a, u64 b) {
    asm("fma.rn.f32x2 %0, %1, %2, %3;" : "=l"(d) : "l"(a), "l"(b), "l"(d));
}
__device__ __forceinline__ void fadd2(u64& d, u64 a, u64 b) {
    asm("add.rn.f32x2 %0, %1, %2;" : "=l"(d) : "l"(a), "l"(b));
}
__device__ __forceinline__ u64 ldg2(const float* p) {
    float2 t = __ldg((const float2*)p); return pack2(t.x, t.y);
}
__device__ __forceinline__ float4 u2_to_f4(u64 a, u64 b) {
    float4 r; unpack2(a, r.x, r.y); unpack2(b, r.z, r.w); return r;
}

static constexpr int THREADS = 128;
static constexpr int BPB     = 8;

// ---- shared layout (floats) ----
// skv[8192]: K rows [0:4096], V rows [4096:8192]; 128 rows x 32 floats,
//            stored as 8 float4-blocks per row, block-rotated by row for banks.
// swb[3072]: phase buffer. P1: Wq(0)/Wk(1024)/Wv(2048). P2: Wo(0).
//            P3: W1(0:2048) + W2half(2048:3072).

__device__ __forceinline__ void cp4(float* dst, const float* __restrict__ src, int n) {
    for (int i = threadIdx.x; i < (n >> 2); i += THREADS)
        ((float4*)dst)[i] = ((const float4*)src)[i];
}

// acc[NP u64] += a * Wrow[0 : 2*NP]   (Wrow 16B aligned, broadcast LDS.128)
template<int NP>
__device__ __forceinline__ void accum_row(const float* __restrict__ Wrow, float a, u64* acc) {
    u64 av = dup2(a);
    const float4* w4 = (const float4*)Wrow;
    #pragma unroll
    for (int p = 0; p < NP / 2; p++) {
        float4 w = w4[p];
        ffma2(acc[2 * p],     av, pack2(w.x, w.y));
        ffma2(acc[2 * p + 1], av, pack2(w.z, w.w));
    }
}

// acc[16] = bias + xs(32 scalars) @ W[32][32]
__device__ __forceinline__ void proj32(const float* __restrict__ Wbase,
                                       const float* __restrict__ bias,
                                       const float* xs, u64* acc) {
    #pragma unroll
    for (int jp = 0; jp < 16; jp++) acc[jp] = ldg2(bias + 2 * jp);
    #pragma unroll
    for (int d = 0; d < 32; d++) accum_row<16>(Wbase + d * 32, xs[d], acc);
}

__device__ __forceinline__ int rowrot(int r) { return ((r & 15) + (r >> 4)) & 7; }

__device__ __forceinline__ void kv_store(float* base, int r, const u64* acc) {
    float4* dst = (float4*)base + r * 8;
    int rot = rowrot(r);
    #pragma unroll
    for (int p = 0; p < 8; p++)
        dst[(p + rot) & 7] = u2_to_f4(acc[2 * p], acc[2 * p + 1]);
}

__global__ void __launch_bounds__(THREADS, 3)
tinyformer_kernel(const float* __restrict__ x,
                  const float* __restrict__ Wq, const float* __restrict__ bq,
                  const float* __restrict__ Wk, const float* __restrict__ bk,
                  const float* __restrict__ Wv, const float* __restrict__ bv,
                  const float* __restrict__ Wo, const float* __restrict__ bo,
                  const float* __restrict__ W1, const float* __restrict__ b1,
                  const float* __restrict__ W2, const float* __restrict__ b2,
                  float* __restrict__ out)
{
    __shared__ __align__(16) float skv[8192];
    __shared__ __align__(16) float swb[3072];

    const int tid = threadIdx.x;
    const int bl  = tid >> 4;      // batch-in-block
    const int s   = tid & 15;      // seq row
    const size_t b = (size_t)blockIdx.x * BPB + bl;
    const size_t row_off = (b * 16 + s) * 32;

    // ---- phase 1 weights ----
    cp4(swb + 0,    Wq, 1024);
    cp4(swb + 1024, Wk, 1024);
    cp4(swb + 2048, Wv, 1024);
    __syncthreads();

    // ---- load x row ----
    float xs[32];
    {
        const float4* xp = (const float4*)(x + row_off);
        #pragma unroll
        for (int i = 0; i < 8; i++) {
            float4 t = xp[i];
            xs[4*i+0] = t.x; xs[4*i+1] = t.y; xs[4*i+2] = t.z; xs[4*i+3] = t.w;
        }
    }

    // ---- projections: K,V -> smem (swizzled), Q -> regs ----
    {
        u64 acc[16];
        proj32(swb + 1024, bk, xs, acc);
        kv_store(skv, tid, acc);
        proj32(swb + 2048, bv, xs, acc);
        kv_store(skv + 4096, tid, acc);
    }
    u64 q[16];
    proj32(swb + 0, bq, xs, q);
    __syncthreads();                       // K/V visible; phase-1 weight reads done

    // ---- phase 2 weights (Wo), issued before attention math ----
    cp4(swb + 0, Wo, 1024);

    // ---- scores ----
    float sc[16];
    {
        const float4* kb = (const float4*)skv + bl * 16 * 8;
        #pragma unroll
        for (int t = 0; t < 16; t++) {
            int rot = rowrot(bl * 16 + t);
            const float4* kr = kb + t * 8;
            u64 a = 0ull;
            #pragma unroll
            for (int p = 0; p < 8; p++) {
                float4 w = kr[(p + rot) & 7];
                ffma2(a, q[2 * p],     pack2(w.x, w.y));
                ffma2(a, q[2 * p + 1], pack2(w.z, w.w));
            }
            float lo, hi; unpack2(a, lo, hi);
            sc[t] = (lo + hi) * 0.17677669529663687f;   // 1/sqrt(32)
        }
    }

    // ---- softmax (in-thread over 16) ----
    {
        float m = sc[0];
        #pragma unroll
        for (int t = 1; t < 16; t++) m = fmaxf(m, sc[t]);
        float sum = 0.f;
        #pragma unroll
        for (int t = 0; t < 16; t++) { sc[t] = __expf(sc[t] - m); sum += sc[t]; }
        float inv = __fdividef(1.f, sum);
        #pragma unroll
        for (int t = 0; t < 16; t++) sc[t] *= inv;
    }

    // ---- context = attn @ V ----
    u64 ctx[16];
    #pragma unroll
    for (int jp = 0; jp < 16; jp++) ctx[jp] = 0ull;
    {
        const float4* vb = (const float4*)skv + 1024 + bl * 16 * 8;
        #pragma unroll
        for (int t = 0; t < 16; t++) {
            int rot = rowrot(bl * 16 + t);
            const float4* vr = vb + t * 8;
            u64 av = dup2(sc[t]);
            #pragma unroll
            for (int p = 0; p < 8; p++) {
                float4 w = vr[(p + rot) & 7];
                ffma2(ctx[2 * p],     av, pack2(w.x, w.y));
                ffma2(ctx[2 * p + 1], av, pack2(w.z, w.w));
            }
        }
    }
    __syncthreads();                       // Wo visible

    // ---- y = x + ctx @ Wo + bo ----
    u64 y[16];
    #pragma unroll
    for (int jp = 0; jp < 16; jp++) y[jp] = ldg2(bo + 2 * jp);
    #pragma unroll
    for (int d2 = 0; d2 < 16; d2++) {
        float c0, c1; unpack2(ctx[d2], c0, c1);
        accum_row<16>(swb + (2 * d2)     * 32, c0, y);
        accum_row<16>(swb + (2 * d2 + 1) * 32, c1, y);
    }
    #pragma unroll
    for (int jp = 0; jp < 16; jp++)
        fadd2(y[jp], y[jp], pack2(xs[2 * jp], xs[2 * jp + 1]));
    __syncthreads();                       // Wo reads done

    // ---- phase 3: W1 + first half of W2 ----
    cp4(swb + 0,    W1, 2048);
    cp4(swb + 2048, W2, 1024);             // W2 rows 0..31
    __syncthreads();

    // ---- z = y + b2; FFN in two 32-wide halves ----
    u64 z[16];
    #pragma unroll
    for (int jp = 0; jp < 16; jp++) { z[jp] = y[jp]; fadd2(z[jp], z[jp], ldg2(b2 + 2 * jp)); }

    // half 0
    {
        u64 hh[16];
        #pragma unroll
        for (int fp = 0; fp < 16; fp++) hh[fp] = ldg2(b1 + 2 * fp);
        #pragma unroll
        for (int d2 = 0; d2 < 16; d2++) {
            float y0, y1; unpack2(y[d2], y0, y1);
            accum_row<16>(swb + (2 * d2)     * 64, y0, hh);
            accum_row<16>(swb + (2 * d2 + 1) * 64, y1, hh);
        }
        #pragma unroll
        for (int fp = 0; fp < 16; fp++) {
            float h0, h1; unpack2(hh[fp], h0, h1);
            h0 = fmaxf(h0, 0.f); h1 = fmaxf(h1, 0.f);
            accum_row<16>(swb + 2048 + (2 * fp)     * 32, h0, z);
            accum_row<16>(swb + 2048 + (2 * fp + 1) * 32, h1, z);
        }
    }
    __syncthreads();                       // W2 half-0 reads done
    cp4(swb + 2048, W2 + 1024, 1024);      // W2 rows 32..63
    __syncthreads();

    // half 1
    {
        u64 hh[16];
        #pragma unroll
        for (int fp = 0; fp < 16; fp++) hh[fp] = ldg2(b1 + 32 + 2 * fp);
        #pragma unroll
        for (int d2 = 0; d2 < 16; d2++) {
            float y0, y1; unpack2(y[d2], y0, y1);
            accum_row<16>(swb + (2 * d2)     * 64 + 32, y0, hh);
            accum_row<16>(swb + (2 * d2 + 1) * 64 + 32, y1, hh);
        }
        #pragma unroll
        for (int fp = 0; fp < 16; fp++) {
            float h0, h1; unpack2(hh[fp], h0, h1);
            h0 = fmaxf(h0, 0.f); h1 = fmaxf(h1, 0.f);
            accum_row<16>(swb + 2048 + (2 * fp)     * 32, h0, z);
            accum_row<16>(swb + 2048 + (2 * fp + 1) * 32, h1, z);
        }
    }

    // ---- store ----
    float4* orow = (float4*)(out + row_off);
    #pragma unroll
    for (int p = 0; p < 8; p++)
        orow[p] = u2_to_f4(z[2 * p], z[2 * p + 1]);
}

extern "C" void kernel_launch(void* const* d_in, const int* in_sizes, int n_in,
                              void* d_out, int out_size)
{
    (void)in_sizes; (void)n_in; (void)out_size;
    const float* x  = (const float*)d_in[0];
    const float* Wq = (const float*)d_in[1];
    const float* bq = (const float*)d_in[2];
    const float* Wk = (const float*)d_in[3];
    const float* bk = (const float*)d_in[4];
    const float* Wv = (const float*)d_in[5];
    const float* bv = (const float*)d_in[6];
    const float* Wo = (const float*)d_in[7];
    const float* bo = (const float*)d_in[8];
    const float* W1 = (const float*)d_in[9];
    const float* b1 = (const float*)d_in[10];
    const float* W2 = (const float*)d_in[11];
    const float* b2 = (const float*)d_in[12];
    float* out = (float*)d_out;

    tinyformer_kernel<<<65536 / BPB, THREADS>>>(
        x, Wq, bq, Wk, bk, Wv, bv, Wo, bo, W1, b1, W2, b2, out);
}